// round 8
// baseline (speedup 1.0000x reference)
#include <cuda_runtime.h>
#include <cuda_fp16.h>
#include <cstdint>

#define BH_NUM 64
#define S_LEN  2048
#define DHEAD  64
#define NT     (S_LEN/64)

// 1/sqrt(64) * log2(e): scores computed directly in log2 domain
#define QSCALE 0.18033688011112042f

// f16 scratch: K tiles [bh][kt][key][word-swizzled], V tiles [bh][kt][dh][seg-rotated]
__device__ __align__(16) unsigned g_Kh[BH_NUM*NT*64*32];   // 16MB
__device__ __align__(16) unsigned g_Vh[BH_NUM*NT*64*32];   // 16MB

__device__ __forceinline__ unsigned packh2(float a, float b){
    __half2 h = __floats2half2_rn(a, b);
    return *reinterpret_cast<unsigned*>(&h);
}

__device__ __forceinline__ void mma_f16(float c[4], const unsigned a[4],
                                        unsigned b0, unsigned b1){
    asm volatile(
        "mma.sync.aligned.m16n8k16.row.col.f32.f16.f16.f32 "
        "{%0,%1,%2,%3}, {%4,%5,%6,%7}, {%8,%9}, {%0,%1,%2,%3};\n"
        : "+f"(c[0]), "+f"(c[1]), "+f"(c[2]), "+f"(c[3])
        : "r"(a[0]), "r"(a[1]), "r"(a[2]), "r"(a[3]), "r"(b0), "r"(b1));
}

__device__ __forceinline__ void ldsm4(unsigned r[4], unsigned saddr){
    asm volatile("ldmatrix.sync.aligned.m8n8.x4.shared.b16 {%0,%1,%2,%3}, [%4];"
        : "=r"(r[0]), "=r"(r[1]), "=r"(r[2]), "=r"(r[3]) : "r"(saddr));
}

#define CP16(sa, ga) asm volatile("cp.async.ca.shared.global [%0], [%1], 16;" :: "r"(sa), "l"(ga) : "memory")
#define CP_COMMIT()  asm volatile("cp.async.commit_group;" ::: "memory")
#define CP_WAIT1()   asm volatile("cp.async.wait_group 1;" ::: "memory")
#define CP_WAIT0()   asm volatile("cp.async.wait_group 0;" ::: "memory")

// ---- prepass: K fp32 -> f16 tiles, word w = (2*c4) ^ ((key&7)<<2) ----
__global__ void conv_k(const float* __restrict__ Kg){
    int idx = blockIdx.x*256 + threadIdx.x;       // [bh][s][c4], c4 = float4 idx 0..15
    int c4 = idx & 15;
    int s  = (idx >> 4) & (S_LEN-1);
    int bh = idx >> 15;
    float4 v = ((const float4*)Kg)[idx];
    int kt = s >> 6, key = s & 63;
    int w = (2*c4) ^ ((key & 7) << 2);
    uint2 p; p.x = packh2(v.x, v.y); p.y = packh2(v.z, v.w);
    *(uint2*)&g_Kh[(((bh*NT + kt)*64 + key)*32) + w] = p;
}

// ---- prepass: V fp32 -> f16 transposed tiles [dh][key], 16B seg (t+dh)&7 ----
__global__ void conv_v(const float* __restrict__ Vg){
    int u  = blockIdx.x*4 + (threadIdx.x >> 6);   // (bh, kt, t) unit
    int dh = threadIdx.x & 63;
    int t  = u & 7;
    int kt = (u >> 3) & (NT-1);
    int bh = u >> 8;
    const float* src = Vg + ((size_t)((bh*S_LEN) + kt*64 + t*8))*64 + dh;
    float f0 = src[0*64], f1 = src[1*64], f2 = src[2*64], f3 = src[3*64];
    float f4 = src[4*64], f5 = src[5*64], f6 = src[6*64], f7 = src[7*64];
    uint4 p;
    p.x = packh2(f0, f1); p.y = packh2(f2, f3);
    p.z = packh2(f4, f5); p.w = packh2(f6, f7);
    int seg = (t + dh) & 7;
    *(uint4*)&g_Vh[(((bh*NT + kt)*64 + dh)*32) + seg*4] = p;
}

// Flash attention v7: cp.async double-buffered f16 tiles + ldmatrix B-frags.
// CTA = 128 q-rows, 4 warps x 32 rows (2 x 16-row tiles). KV tile = 64 keys.
__global__ void __launch_bounds__(128, 2)
sdpa_flash_f16_v7(const float* __restrict__ Qg, float* __restrict__ Og)
{
    __shared__ unsigned sm[8192];    // 32KB: Ks0|Ks1|Vs0|Vs1, 2048 words each

    const int tid  = threadIdx.x;
    const int w    = tid >> 5;
    const int lane = tid & 31;
    const int qg   = lane >> 2;
    const int rg   = lane & 3;
    const int swzA = qg << 2;

    // ldmatrix lane constants: m = lane/8 (matrix), r = lane%8 (row)
    const int m_   = lane >> 3;
    const int r_   = lane & 7;
    const int joff = (m_ >> 1) << 3;       // 0 or 8: second matrix pair = j+1 block
    const int h_   = m_ & 1;               // 0: b0 half, 1: b1 half
    const unsigned rowoff = (unsigned)(joff + r_) * 128;   // byte offset of row
    const unsigned r16    = (unsigned)r_ << 4;
    const unsigned h16    = (unsigned)h_ << 4;
    const int      sl     = h_ + r_;       // V segment base

    const int qt = blockIdx.x;
    const int bh = blockIdx.y;
    const size_t base = (size_t)bh * S_LEN * DHEAD;

    const unsigned smBase = (unsigned)__cvta_generic_to_shared(sm);

    // ---- prologue: start cp.async of tile 0 into buffer 0 ----
    {
        const char* kg = (const char*)g_Kh + (size_t)(bh*NT + 0)*8192;
        const char* vg = (const char*)g_Vh + (size_t)(bh*NT + 0)*8192;
        #pragma unroll
        for (int i = 0; i < 4; i++){
            int ch = tid + i*128;
            CP16(smBase         + ch*16, kg + ch*16);
            CP16(smBase + 16384 + ch*16, vg + ch*16);
        }
        CP_COMMIT();
    }

    // ---- stage Q tile into buffer 1 regions (scratch), K-style swizzle ----
    {
        const float4* Qt4 = (const float4*)(Qg + base + (size_t)qt*128*DHEAD);
        unsigned* Ks1 = sm + 2048;
        unsigned* Vs1 = sm + 6144;
        #pragma unroll
        for (int i = 0; i < 16; i++){
            int idx = tid + i*128;
            int row = idx >> 4;
            int c   = idx & 15;
            float4 v = Qt4[idx];
            unsigned* dst = (row < 64) ? Ks1 : Vs1;
            int r = row & 63;
            int d = r*32 + ((2*c) ^ ((r & 7) << 2));
            uint2 p; p.x = packh2(v.x*QSCALE, v.y*QSCALE);
                     p.y = packh2(v.z*QSCALE, v.w*QSCALE);
            *(uint2*)&dst[d] = p;
        }
    }
    __syncthreads();

    // Q fragments: 2 row-tiles x 4 k-chunks x 4 regs
    unsigned qa[2][4][4];
    #pragma unroll
    for (int rt = 0; rt < 2; rt++){
        const int grow = w*32 + rt*16 + qg;
        const unsigned* src = (grow < 64) ? (sm + 2048) : (sm + 6144);
        const int r0 = grow & 63;
        #pragma unroll
        for (int kc = 0; kc < 4; kc++){
            qa[rt][kc][0] = src[ r0    *32 + ((8*kc   + rg) ^ swzA)];
            qa[rt][kc][1] = src[(r0+8) *32 + ((8*kc   + rg) ^ swzA)];
            qa[rt][kc][2] = src[ r0    *32 + ((8*kc+4 + rg) ^ swzA)];
            qa[rt][kc][3] = src[(r0+8) *32 + ((8*kc+4 + rg) ^ swzA)];
        }
    }
    __syncthreads();   // buffer 1 free for tile 1 fill

    float o[2][8][4];
    #pragma unroll
    for (int rt = 0; rt < 2; rt++)
        #pragma unroll
        for (int j = 0; j < 8; j++){ o[rt][j][0]=0.f; o[rt][j][1]=0.f; o[rt][j][2]=0.f; o[rt][j][3]=0.f; }
    float m0[2] = {-1e30f,-1e30f}, m1[2] = {-1e30f,-1e30f};
    float l0[2] = {0.f,0.f},       l1[2] = {0.f,0.f};

    for (int kt = 0; kt < NT; kt++){
        const int b = kt & 1;

        // ---- issue cp.async for tile kt+1 into the other buffer ----
        if (kt + 1 < NT){
            const int bn = b ^ 1;
            const char* kg = (const char*)g_Kh + (size_t)(bh*NT + kt+1)*8192;
            const char* vg = (const char*)g_Vh + (size_t)(bh*NT + kt+1)*8192;
            #pragma unroll
            for (int i = 0; i < 4; i++){
                int ch = tid + i*128;
                CP16(smBase + bn*8192         + ch*16, kg + ch*16);
                CP16(smBase + bn*8192 + 16384 + ch*16, vg + ch*16);
            }
            CP_COMMIT();
            CP_WAIT1();             // tile kt complete (kt+1 may be in flight)
        } else {
            CP_WAIT0();
        }
        __syncthreads();            // tile kt visible to all warps

        const unsigned ksb = smBase + b*8192;
        const unsigned vsb = smBase + b*8192 + 16384;

        // ---- S = Q K^T (log2 domain), B via ldmatrix.x4 ----
        float sc[2][8][4];
        #pragma unroll
        for (int rt = 0; rt < 2; rt++)
            #pragma unroll
            for (int j = 0; j < 8; j++){ sc[rt][j][0]=0.f; sc[rt][j][1]=0.f; sc[rt][j][2]=0.f; sc[rt][j][3]=0.f; }
        #pragma unroll
        for (int kc = 0; kc < 4; kc++){
            const unsigned wb = ((unsigned)(32*kc) + h16) ^ r16;
            #pragma unroll
            for (int j0 = 0; j0 < 4; j0++){
                unsigned bq[4];
                ldsm4(bq, ksb + j0*2048 + rowoff + wb);
                mma_f16(sc[0][2*j0  ], qa[0][kc], bq[0], bq[1]);
                mma_f16(sc[1][2*j0  ], qa[1][kc], bq[0], bq[1]);
                mma_f16(sc[0][2*j0+1], qa[0][kc], bq[2], bq[3]);
                mma_f16(sc[1][2*j0+1], qa[1][kc], bq[2], bq[3]);
            }
        }

        // ---- online softmax (v5 ordering), exps -> pa registers ----
        unsigned pa[2][4][4];
        #pragma unroll
        for (int rt = 0; rt < 2; rt++){
            float tm0 = -1e30f, tm1 = -1e30f;
            #pragma unroll
            for (int j = 0; j < 8; j++){
                tm0 = fmaxf(tm0, fmaxf(sc[rt][j][0], sc[rt][j][1]));
                tm1 = fmaxf(tm1, fmaxf(sc[rt][j][2], sc[rt][j][3]));
            }
            tm0 = fmaxf(tm0, __shfl_xor_sync(0xffffffffu, tm0, 1));
            tm0 = fmaxf(tm0, __shfl_xor_sync(0xffffffffu, tm0, 2));
            tm1 = fmaxf(tm1, __shfl_xor_sync(0xffffffffu, tm1, 1));
            tm1 = fmaxf(tm1, __shfl_xor_sync(0xffffffffu, tm1, 2));
            float nm0 = fmaxf(m0[rt], tm0), nm1 = fmaxf(m1[rt], tm1);
            float al0 = exp2f(m0[rt] - nm0), al1 = exp2f(m1[rt] - nm1);
            m0[rt] = nm0; m1[rt] = nm1;

            float rs0 = 0.f, rs1 = 0.f;
            #pragma unroll
            for (int kc = 0; kc < 4; kc++){
                float e00 = exp2f(sc[rt][2*kc  ][0] - nm0);
                float e01 = exp2f(sc[rt][2*kc  ][1] - nm0);
                float e02 = exp2f(sc[rt][2*kc  ][2] - nm1);
                float e03 = exp2f(sc[rt][2*kc  ][3] - nm1);
                float e10 = exp2f(sc[rt][2*kc+1][0] - nm0);
                float e11 = exp2f(sc[rt][2*kc+1][1] - nm0);
                float e12 = exp2f(sc[rt][2*kc+1][2] - nm1);
                float e13 = exp2f(sc[rt][2*kc+1][3] - nm1);
                rs0 += e00 + e01 + e10 + e11;
                rs1 += e02 + e03 + e12 + e13;
                pa[rt][kc][0] = packh2(e00, e01);
                pa[rt][kc][1] = packh2(e02, e03);
                pa[rt][kc][2] = packh2(e10, e11);
                pa[rt][kc][3] = packh2(e12, e13);
            }
            #pragma unroll
            for (int j = 0; j < 8; j++){
                o[rt][j][0]*=al0; o[rt][j][1]*=al0; o[rt][j][2]*=al1; o[rt][j][3]*=al1;
            }
            rs0 += __shfl_xor_sync(0xffffffffu, rs0, 1);
            rs0 += __shfl_xor_sync(0xffffffffu, rs0, 2);
            rs1 += __shfl_xor_sync(0xffffffffu, rs1, 1);
            rs1 += __shfl_xor_sync(0xffffffffu, rs1, 2);
            l0[rt] = l0[rt]*al0 + rs0;
            l1[rt] = l1[rt]*al1 + rs1;
        }

        // ---- O += P V, B via ldmatrix.x4 on segment-rotated V^T ----
        #pragma unroll
        for (int kc = 0; kc < 4; kc++){
            const unsigned segb = (unsigned)((2*kc + sl) & 7) << 4;
            #pragma unroll
            for (int j0 = 0; j0 < 4; j0++){
                unsigned bv[4];
                ldsm4(bv, vsb + j0*2048 + rowoff + segb);
                mma_f16(o[0][2*j0  ], pa[0][kc], bv[0], bv[1]);
                mma_f16(o[1][2*j0  ], pa[1][kc], bv[0], bv[1]);
                mma_f16(o[0][2*j0+1], pa[0][kc], bv[2], bv[3]);
                mma_f16(o[1][2*j0+1], pa[1][kc], bv[2], bv[3]);
            }
        }
        __syncthreads();   // all warps done with buffer b before it is refilled
    }

    // ---- epilogue: O /= l, write fp32 ----
    float2* Od = (float2*)(Og + base);
    #pragma unroll
    for (int rt = 0; rt < 2; rt++){
        float inv0 = 1.f / l0[rt], inv1 = 1.f / l1[rt];
        const int row0 = qt*128 + w*32 + rt*16 + qg;
        #pragma unroll
        for (int j = 0; j < 8; j++){
            int d = j*8 + 2*rg;
            Od[( row0   *64 + d) >> 1] = make_float2(o[rt][j][0]*inv0, o[rt][j][1]*inv0);
            Od[((row0+8)*64 + d) >> 1] = make_float2(o[rt][j][2]*inv1, o[rt][j][3]*inv1);
        }
    }
}

extern "C" void kernel_launch(void* const* d_in, const int* in_sizes, int n_in,
                              void* d_out, int out_size){
    const float* Q = (const float*)d_in[0];
    const float* K = (const float*)d_in[1];
    const float* V = (const float*)d_in[2];
    float* O = (float*)d_out;

    conv_k<<<(BH_NUM*S_LEN*16)/256, 256>>>(K);          // 8192 blocks
    conv_v<<<(BH_NUM*NT*8)/4, 256>>>(V);                // 4096 blocks
    dim3 grid(S_LEN/128, BH_NUM);
    sdpa_flash_f16_v7<<<grid, 128>>>(Q, O);
}

// round 13
// speedup vs baseline: 1.2101x; 1.2101x over previous
#include <cuda_runtime.h>
#include <cuda_fp16.h>
#include <cstdint>

#define BH_NUM 64
#define S_LEN  2048
#define DHEAD  64

// 1/sqrt(64) * log2(e): scores computed directly in log2 domain
#define QSCALE 0.18033688011112042f

__device__ __forceinline__ unsigned packh2(float a, float b){
    __half2 h = __floats2half2_rn(a, b);
    return *reinterpret_cast<unsigned*>(&h);
}

// two exps in one MUFU op: f16x2 in log2 domain -> f16x2 probabilities
__device__ __forceinline__ unsigned ex2h2(unsigned d){
    unsigned r;
    asm("ex2.approx.f16x2 %0, %1;" : "=r"(r) : "r"(d));
    return r;
}

__device__ __forceinline__ float2 h2f2(unsigned u){
    __half2 h = *reinterpret_cast<__half2*>(&u);
    return __half22float2(h);
}

// D = A*B + D,  m16n8k16 f16 inputs, fp32 accumulate
__device__ __forceinline__ void mma_f16(float c[4], const unsigned a[4],
                                        unsigned b0, unsigned b1){
    asm volatile(
        "mma.sync.aligned.m16n8k16.row.col.f32.f16.f16.f32 "
        "{%0,%1,%2,%3}, {%4,%5,%6,%7}, {%8,%9}, {%0,%1,%2,%3};\n"
        : "+f"(c[0]), "+f"(c[1]), "+f"(c[2]), "+f"(c[3])
        : "r"(a[0]), "r"(a[1]), "r"(a[2]), "r"(a[3]), "r"(b0), "r"(b1));
}

// Flash attention v8 = v5 structure + log2-domain scores + f16x2 ex2.
//  CTA = 128 q-rows, 4 warps x 32 rows (2 x 16-row tiles). KV tile = 64 keys.
//  Ks: K tile [key][d] f16, rows = 32 words (128B), word w stored at w ^ ((key&7)<<2).
//  Vs: V tile TRANSPOSED [dh][key] f16, word w at w ^ (((dh&7)<<2) ^ ((dh>>3)&3)).
//  P lives entirely in registers (f16 C-frag == A-frag layout).
__global__ void __launch_bounds__(128, 2)
sdpa_flash_f16_v8(const float* __restrict__ Qg, const float* __restrict__ Kg,
                  const float* __restrict__ Vg, float* __restrict__ Og)
{
    __shared__ unsigned Ks[64*32];   // 8KB
    __shared__ unsigned Vs[64*32];   // 8KB

    const int tid  = threadIdx.x;
    const int w    = tid >> 5;
    const int lane = tid & 31;
    const int qg   = lane >> 2;      // 0..7
    const int rg   = lane & 3;       // 0..3
    const int swzA = qg << 2;

    const int qt = blockIdx.x;       // 0..15
    const int bh = blockIdx.y;       // 0..63

    const size_t base = (size_t)bh * S_LEN * DHEAD;

    // ---- stage Q tile (128x64 fp32 -> f16, QSCALE folded): rows 0..63 -> Ks, 64..127 -> Vs ----
    {
        const float4* Qt4 = (const float4*)(Qg + base + (size_t)qt*128*DHEAD);
        #pragma unroll
        for (int i = 0; i < 16; i++){
            int idx = tid + i*128;
            int row = idx >> 4;
            int c   = idx & 15;
            float4 v = Qt4[idx];
            unsigned* dst = (row < 64) ? Ks : Vs;
            int r = row & 63;
            int d = r*32 + ((2*c) ^ ((r & 7) << 2));
            uint2 p; p.x = packh2(v.x*QSCALE, v.y*QSCALE);
                     p.y = packh2(v.z*QSCALE, v.w*QSCALE);
            *(uint2*)&dst[d] = p;
        }
    }
    __syncthreads();

    // Q fragments: 2 row-tiles x 4 k-chunks x 4 regs (f16x2)
    unsigned qa[2][4][4];
    #pragma unroll
    for (int rt = 0; rt < 2; rt++){
        const int grow = w*32 + rt*16 + qg;
        const unsigned* src = (grow < 64) ? Ks : Vs;
        const int r0 = grow & 63;
        #pragma unroll
        for (int kc = 0; kc < 4; kc++){
            qa[rt][kc][0] = src[ r0    *32 + ((8*kc   + rg) ^ swzA)];
            qa[rt][kc][1] = src[(r0+8) *32 + ((8*kc   + rg) ^ swzA)];
            qa[rt][kc][2] = src[ r0    *32 + ((8*kc+4 + rg) ^ swzA)];
            qa[rt][kc][3] = src[(r0+8) *32 + ((8*kc+4 + rg) ^ swzA)];
        }
    }
    __syncthreads();

    float o[2][8][4];
    #pragma unroll
    for (int rt = 0; rt < 2; rt++)
        #pragma unroll
        for (int j = 0; j < 8; j++){ o[rt][j][0]=0.f; o[rt][j][1]=0.f; o[rt][j][2]=0.f; o[rt][j][3]=0.f; }
    float m0[2] = {-1e30f,-1e30f}, m1[2] = {-1e30f,-1e30f};
    float l0[2] = {0.f,0.f},       l1[2] = {0.f,0.f};

    const int vdh   = tid & 63;
    const int vgrp  = tid >> 6;
    const int vs_sw = ((vdh & 7) << 2) ^ ((vdh >> 3) & 3);

    for (int kt = 0; kt < S_LEN/64; kt++){
        // ---- fill K tile [key][d] (f16, swizzled) ----
        const float4* Kt4 = (const float4*)(Kg + base + (size_t)kt*64*DHEAD);
        #pragma unroll
        for (int i = 0; i < 8; i++){
            int idx = tid + i*128;
            int row = idx >> 4;
            int c   = idx & 15;
            float4 kv = Kt4[idx];
            int d = row*32 + ((2*c) ^ ((row & 7) << 2));
            uint2 p; p.x = packh2(kv.x, kv.y); p.y = packh2(kv.z, kv.w);
            *(uint2*)&Ks[d] = p;
        }
        // ---- fill V tile TRANSPOSED [dh][key] (f16, swizzled) ----
        {
            const float* Vt = Vg + base + (size_t)kt*64*DHEAD;
            #pragma unroll
            for (int i = 0; i < 8; i++){
                int k0 = vgrp*4 + i*8;
                float v0 = Vt[(k0+0)*64 + vdh];
                float v1 = Vt[(k0+1)*64 + vdh];
                float v2 = Vt[(k0+2)*64 + vdh];
                float v3 = Vt[(k0+3)*64 + vdh];
                Vs[vdh*32 + (((k0>>1)  ) ^ vs_sw)] = packh2(v0, v1);
                Vs[vdh*32 + (((k0>>1)+1) ^ vs_sw)] = packh2(v2, v3);
            }
        }
        __syncthreads();

        // ---- S = Q K^T (log2 domain) : each B load feeds both row-tiles ----
        float sc[2][8][4];
        #pragma unroll
        for (int rt = 0; rt < 2; rt++)
            #pragma unroll
            for (int j = 0; j < 8; j++){ sc[rt][j][0]=0.f; sc[rt][j][1]=0.f; sc[rt][j][2]=0.f; sc[rt][j][3]=0.f; }
        #pragma unroll
        for (int kc = 0; kc < 4; kc++){
            #pragma unroll
            for (int j = 0; j < 8; j++){
                const unsigned* kr = &Ks[(8*j + qg)*32];
                unsigned b0 = kr[(8*kc   + rg) ^ swzA];
                unsigned b1 = kr[(8*kc+4 + rg) ^ swzA];
                mma_f16(sc[0][j], qa[0][kc], b0, b1);
                mma_f16(sc[1][j], qa[1][kc], b0, b1);
            }
        }

        // ---- online softmax; subtract in f32, exp two-at-a-time in f16x2 (MUFU halved) ----
        unsigned pa[2][4][4];
        #pragma unroll
        for (int rt = 0; rt < 2; rt++){
            float tm0 = -1e30f, tm1 = -1e30f;
            #pragma unroll
            for (int j = 0; j < 8; j++){
                tm0 = fmaxf(tm0, fmaxf(sc[rt][j][0], sc[rt][j][1]));
                tm1 = fmaxf(tm1, fmaxf(sc[rt][j][2], sc[rt][j][3]));
            }
            tm0 = fmaxf(tm0, __shfl_xor_sync(0xffffffffu, tm0, 1));
            tm0 = fmaxf(tm0, __shfl_xor_sync(0xffffffffu, tm0, 2));
            tm1 = fmaxf(tm1, __shfl_xor_sync(0xffffffffu, tm1, 1));
            tm1 = fmaxf(tm1, __shfl_xor_sync(0xffffffffu, tm1, 2));
            float nm0 = fmaxf(m0[rt], tm0), nm1 = fmaxf(m1[rt], tm1);
            float al0 = exp2f(m0[rt] - nm0), al1 = exp2f(m1[rt] - nm1);
            m0[rt] = nm0; m1[rt] = nm1;

            float rs0 = 0.f, rs1 = 0.f;
            #pragma unroll
            for (int kc = 0; kc < 4; kc++){
                // pack (s - m) pairs, one MUFU ex2 per pair -> pa entries directly
                unsigned e0 = ex2h2(packh2(sc[rt][2*kc  ][0] - nm0, sc[rt][2*kc  ][1] - nm0));
                unsigned e1 = ex2h2(packh2(sc[rt][2*kc  ][2] - nm1, sc[rt][2*kc  ][3] - nm1));
                unsigned e2 = ex2h2(packh2(sc[rt][2*kc+1][0] - nm0, sc[rt][2*kc+1][1] - nm0));
                unsigned e3 = ex2h2(packh2(sc[rt][2*kc+1][2] - nm1, sc[rt][2*kc+1][3] - nm1));
                pa[rt][kc][0] = e0;
                pa[rt][kc][1] = e1;
                pa[rt][kc][2] = e2;
                pa[rt][kc][3] = e3;
                // row sums in f32 (unpack is cheap F2F; keeps l precision)
                float2 f0 = h2f2(e0), f1 = h2f2(e1), f2 = h2f2(e2), f3 = h2f2(e3);
                rs0 += (f0.x + f0.y) + (f2.x + f2.y);
                rs1 += (f1.x + f1.y) + (f3.x + f3.y);
            }
            #pragma unroll
            for (int j = 0; j < 8; j++){
                o[rt][j][0]*=al0; o[rt][j][1]*=al0; o[rt][j][2]*=al1; o[rt][j][3]*=al1;
            }
            rs0 += __shfl_xor_sync(0xffffffffu, rs0, 1);
            rs0 += __shfl_xor_sync(0xffffffffu, rs0, 2);
            rs1 += __shfl_xor_sync(0xffffffffu, rs1, 1);
            rs1 += __shfl_xor_sync(0xffffffffu, rs1, 2);
            l0[rt] = l0[rt]*al0 + rs0;
            l1[rt] = l1[rt]*al1 + rs1;
        }

        // ---- O += P V : V^T in smem, each B load feeds both row-tiles ----
        #pragma unroll
        for (int kc = 0; kc < 4; kc++){
            #pragma unroll
            for (int j = 0; j < 8; j++){
                const unsigned* vr = &Vs[(8*j + qg)*32];
                int vw = swzA ^ (j & 3);
                unsigned b0 = vr[(8*kc   + rg) ^ vw];
                unsigned b1 = vr[(8*kc+4 + rg) ^ vw];
                mma_f16(o[0][j], pa[0][kc], b0, b1);
                mma_f16(o[1][j], pa[1][kc], b0, b1);
            }
        }
        __syncthreads();   // protect Ks/Vs before next tile's fill
    }

    // ---- epilogue: O /= l, write fp32 ----
    float2* Od = (float2*)(Og + base);
    #pragma unroll
    for (int rt = 0; rt < 2; rt++){
        float inv0 = 1.f / l0[rt], inv1 = 1.f / l1[rt];
        const int row0 = qt*128 + w*32 + rt*16 + qg;
        #pragma unroll
        for (int j = 0; j < 8; j++){
            int d = j*8 + 2*rg;
            Od[( row0   *64 + d) >> 1] = make_float2(o[rt][j][0]*inv0, o[rt][j][1]*inv0);
            Od[((row0+8)*64 + d) >> 1] = make_float2(o[rt][j][2]*inv1, o[rt][j][3]*inv1);
        }
    }
}

extern "C" void kernel_launch(void* const* d_in, const int* in_sizes, int n_in,
                              void* d_out, int out_size){
    const float* Q = (const float*)d_in[0];
    const float* K = (const float*)d_in[1];
    const float* V = (const float*)d_in[2];
    float* O = (float*)d_out;
    dim3 grid(S_LEN/128, BH_NUM);   // q-tile fastest -> same-bh CTAs share K/V in L2
    sdpa_flash_f16_v8<<<grid, 128>>>(Q, K, V, O);
}

// round 14
// speedup vs baseline: 1.3687x; 1.1311x over previous
#include <cuda_runtime.h>
#include <cuda_fp16.h>
#include <cstdint>

#define BH_NUM 64
#define S_LEN  2048
#define DHEAD  64
#define NT     (S_LEN/64)

// 1/sqrt(64) * log2(e): scores computed directly in log2 domain
#define QSCALE 0.18033688011112042f

// f16 tile images, exact smem layouts, filled by prepass:
//  K tile: word (2c)^((key&7)<<2) at row key   (rows of 32 words)
//  V tile: word kk^vs_sw at row dh, kk = keypair, vs_sw = ((dh&7)<<2)^((dh>>3)&3)
__device__ __align__(16) unsigned g_Kh[BH_NUM*NT*64*32];   // 16MB
__device__ __align__(16) unsigned g_Vh[BH_NUM*NT*64*32];   // 16MB

__device__ __forceinline__ unsigned packh2(float a, float b){
    __half2 h = __floats2half2_rn(a, b);
    return *reinterpret_cast<unsigned*>(&h);
}

__device__ __forceinline__ unsigned ex2h2(unsigned d){
    unsigned r;
    asm("ex2.approx.f16x2 %0, %1;" : "=r"(r) : "r"(d));
    return r;
}

__device__ __forceinline__ float2 h2f2(unsigned u){
    __half2 h = *reinterpret_cast<__half2*>(&u);
    return __half22float2(h);
}

__device__ __forceinline__ void mma_f16(float c[4], const unsigned a[4],
                                        unsigned b0, unsigned b1){
    asm volatile(
        "mma.sync.aligned.m16n8k16.row.col.f32.f16.f16.f32 "
        "{%0,%1,%2,%3}, {%4,%5,%6,%7}, {%8,%9}, {%0,%1,%2,%3};\n"
        : "+f"(c[0]), "+f"(c[1]), "+f"(c[2]), "+f"(c[3])
        : "r"(a[0]), "r"(a[1]), "r"(a[2]), "r"(a[3]), "r"(b0), "r"(b1));
}

#define CP16(sa, ga) asm volatile("cp.async.ca.shared.global [%0], [%1], 16;" :: "r"(sa), "l"(ga) : "memory")
#define CP_COMMIT()  asm volatile("cp.async.commit_group;" ::: "memory")
#define CP_WAIT1()   asm volatile("cp.async.wait_group 1;" ::: "memory")
#define CP_WAIT0()   asm volatile("cp.async.wait_group 0;" ::: "memory")

// ---- prepass: K fp32 -> f16 tile image, word w = (2*c4) ^ ((key&7)<<2) ----
__global__ void conv_k(const float* __restrict__ Kg){
    int idx = blockIdx.x*256 + threadIdx.x;       // [bh][s][c4]
    int c4 = idx & 15;
    int s  = (idx >> 4) & (S_LEN-1);
    int bh = idx >> 15;
    float4 v = ((const float4*)Kg)[idx];
    int kt = s >> 6, key = s & 63;
    int w = (2*c4) ^ ((key & 7) << 2);
    uint2 p; p.x = packh2(v.x, v.y); p.y = packh2(v.z, v.w);
    *(uint2*)&g_Kh[(((bh*NT + kt)*64 + key)*32) + w] = p;
}

// ---- prepass: V fp32 -> f16 transposed image [dh][keypair], word kk ^ vs_sw ----
__global__ void conv_v(const float* __restrict__ Vg){
    int u  = blockIdx.x*4 + (threadIdx.x >> 6);   // (bh, kt, t) unit; t = key octet
    int dh = threadIdx.x & 63;
    int t  = u & 7;
    int kt = (u >> 3) & (NT-1);
    int bh = u >> 8;
    const float* src = Vg + ((size_t)(bh*S_LEN + kt*64 + t*8))*64 + dh;
    unsigned* dst = g_Vh + (size_t)(bh*NT + kt)*2048 + dh*32;
    int vs_sw = ((dh & 7) << 2) ^ ((dh >> 3) & 3);
    #pragma unroll
    for (int p = 0; p < 4; p++){
        float a = src[(2*p)*64], b = src[(2*p+1)*64];
        dst[(t*4 + p) ^ vs_sw] = packh2(a, b);
    }
}

// Flash attention v9 = v8 hot loop + cp.async double-buffered prepassed tiles.
// CTA = 128 q-rows, 4 warps x 32 rows (2 x 16-row tiles). KV tile = 64 keys.
// Smem (32KB): K0 | K1 | V0 | V1, 2048 words each. Q staged via K1/V1 regions.
__global__ void __launch_bounds__(128, 2)
sdpa_flash_f16_v9(const float* __restrict__ Qg, float* __restrict__ Og)
{
    __shared__ unsigned sm[8192];

    const int tid  = threadIdx.x;
    const int w    = tid >> 5;
    const int lane = tid & 31;
    const int qg   = lane >> 2;      // 0..7
    const int rg   = lane & 3;       // 0..3
    const int swzA = qg << 2;

    const int qt = blockIdx.x;       // 0..15
    const int bh = blockIdx.y;       // 0..63
    const size_t base = (size_t)bh * S_LEN * DHEAD;

    const unsigned smBase = (unsigned)__cvta_generic_to_shared(sm);

    // ---- prologue: cp.async tile 0 -> buffer 0 ----
    {
        const char* kg = (const char*)g_Kh + (size_t)(bh*NT)*8192;
        const char* vg = (const char*)g_Vh + (size_t)(bh*NT)*8192;
        #pragma unroll
        for (int i = 0; i < 4; i++){
            int ch = tid + i*128;
            CP16(smBase         + ch*16, kg + ch*16);
            CP16(smBase + 16384 + ch*16, vg + ch*16);
        }
        CP_COMMIT();
    }

    // ---- stage Q tile into buffer-1 regions (K1: rows 0..63, V1: rows 64..127) ----
    {
        const float4* Qt4 = (const float4*)(Qg + base + (size_t)qt*128*DHEAD);
        unsigned* Ks1 = sm + 2048;
        unsigned* Vs1 = sm + 6144;
        #pragma unroll
        for (int i = 0; i < 16; i++){
            int idx = tid + i*128;
            int row = idx >> 4;
            int c   = idx & 15;
            float4 v = Qt4[idx];
            unsigned* dst = (row < 64) ? Ks1 : Vs1;
            int r = row & 63;
            int d = r*32 + ((2*c) ^ ((r & 7) << 2));
            uint2 p; p.x = packh2(v.x*QSCALE, v.y*QSCALE);
                     p.y = packh2(v.z*QSCALE, v.w*QSCALE);
            *(uint2*)&dst[d] = p;
        }
    }
    __syncthreads();

    // Q fragments: 2 row-tiles x 4 k-chunks x 4 regs (f16x2)
    unsigned qa[2][4][4];
    #pragma unroll
    for (int rt = 0; rt < 2; rt++){
        const int grow = w*32 + rt*16 + qg;
        const unsigned* src = (grow < 64) ? (sm + 2048) : (sm + 6144);
        const int r0 = grow & 63;
        #pragma unroll
        for (int kc = 0; kc < 4; kc++){
            qa[rt][kc][0] = src[ r0    *32 + ((8*kc   + rg) ^ swzA)];
            qa[rt][kc][1] = src[(r0+8) *32 + ((8*kc   + rg) ^ swzA)];
            qa[rt][kc][2] = src[ r0    *32 + ((8*kc+4 + rg) ^ swzA)];
            qa[rt][kc][3] = src[(r0+8) *32 + ((8*kc+4 + rg) ^ swzA)];
        }
    }
    __syncthreads();   // buffer 1 now free for tile 1's fill

    float o[2][8][4];
    #pragma unroll
    for (int rt = 0; rt < 2; rt++)
        #pragma unroll
        for (int j = 0; j < 8; j++){ o[rt][j][0]=0.f; o[rt][j][1]=0.f; o[rt][j][2]=0.f; o[rt][j][3]=0.f; }
    float m0[2] = {-1e30f,-1e30f}, m1[2] = {-1e30f,-1e30f};
    float l0[2] = {0.f,0.f},       l1[2] = {0.f,0.f};

    for (int kt = 0; kt < NT; kt++){
        const int b = kt & 1;

        // ---- issue cp.async for tile kt+1 into the other buffer, then wait tile kt ----
        if (kt + 1 < NT){
            const int bn = b ^ 1;
            const char* kg = (const char*)g_Kh + (size_t)(bh*NT + kt+1)*8192;
            const char* vg = (const char*)g_Vh + (size_t)(bh*NT + kt+1)*8192;
            #pragma unroll
            for (int i = 0; i < 4; i++){
                int ch = tid + i*128;
                CP16(smBase + bn*8192         + ch*16, kg + ch*16);
                CP16(smBase + bn*8192 + 16384 + ch*16, vg + ch*16);
            }
            CP_COMMIT();
            CP_WAIT1();
        } else {
            CP_WAIT0();
        }
        __syncthreads();            // tile kt visible to all warps

        const unsigned* Ksb = sm + b*2048;
        const unsigned* Vsb = sm + 4096 + b*2048;

        // ---- S = Q K^T (log2 domain) : each B load feeds both row-tiles ----
        float sc[2][8][4];
        #pragma unroll
        for (int rt = 0; rt < 2; rt++)
            #pragma unroll
            for (int j = 0; j < 8; j++){ sc[rt][j][0]=0.f; sc[rt][j][1]=0.f; sc[rt][j][2]=0.f; sc[rt][j][3]=0.f; }
        #pragma unroll
        for (int kc = 0; kc < 4; kc++){
            #pragma unroll
            for (int j = 0; j < 8; j++){
                const unsigned* kr = &Ksb[(8*j + qg)*32];
                unsigned b0 = kr[(8*kc   + rg) ^ swzA];
                unsigned b1 = kr[(8*kc+4 + rg) ^ swzA];
                mma_f16(sc[0][j], qa[0][kc], b0, b1);
                mma_f16(sc[1][j], qa[1][kc], b0, b1);
            }
        }

        // ---- online softmax; subtract in f32, exp two-at-a-time in f16x2 ----
        unsigned pa[2][4][4];
        #pragma unroll
        for (int rt = 0; rt < 2; rt++){
            float tm0 = -1e30f, tm1 = -1e30f;
            #pragma unroll
            for (int j = 0; j < 8; j++){
                tm0 = fmaxf(tm0, fmaxf(sc[rt][j][0], sc[rt][j][1]));
                tm1 = fmaxf(tm1, fmaxf(sc[rt][j][2], sc[rt][j][3]));
            }
            tm0 = fmaxf(tm0, __shfl_xor_sync(0xffffffffu, tm0, 1));
            tm0 = fmaxf(tm0, __shfl_xor_sync(0xffffffffu, tm0, 2));
            tm1 = fmaxf(tm1, __shfl_xor_sync(0xffffffffu, tm1, 1));
            tm1 = fmaxf(tm1, __shfl_xor_sync(0xffffffffu, tm1, 2));
            float nm0 = fmaxf(m0[rt], tm0), nm1 = fmaxf(m1[rt], tm1);
            float al0 = exp2f(m0[rt] - nm0), al1 = exp2f(m1[rt] - nm1);
            m0[rt] = nm0; m1[rt] = nm1;

            float rs0 = 0.f, rs1 = 0.f;
            #pragma unroll
            for (int kc = 0; kc < 4; kc++){
                unsigned e0 = ex2h2(packh2(sc[rt][2*kc  ][0] - nm0, sc[rt][2*kc  ][1] - nm0));
                unsigned e1 = ex2h2(packh2(sc[rt][2*kc  ][2] - nm1, sc[rt][2*kc  ][3] - nm1));
                unsigned e2 = ex2h2(packh2(sc[rt][2*kc+1][0] - nm0, sc[rt][2*kc+1][1] - nm0));
                unsigned e3 = ex2h2(packh2(sc[rt][2*kc+1][2] - nm1, sc[rt][2*kc+1][3] - nm1));
                pa[rt][kc][0] = e0;
                pa[rt][kc][1] = e1;
                pa[rt][kc][2] = e2;
                pa[rt][kc][3] = e3;
                float2 f0 = h2f2(e0), f1 = h2f2(e1), f2 = h2f2(e2), f3 = h2f2(e3);
                rs0 += (f0.x + f0.y) + (f2.x + f2.y);
                rs1 += (f1.x + f1.y) + (f3.x + f3.y);
            }
            #pragma unroll
            for (int j = 0; j < 8; j++){
                o[rt][j][0]*=al0; o[rt][j][1]*=al0; o[rt][j][2]*=al1; o[rt][j][3]*=al1;
            }
            rs0 += __shfl_xor_sync(0xffffffffu, rs0, 1);
            rs0 += __shfl_xor_sync(0xffffffffu, rs0, 2);
            rs1 += __shfl_xor_sync(0xffffffffu, rs1, 1);
            rs1 += __shfl_xor_sync(0xffffffffu, rs1, 2);
            l0[rt] = l0[rt]*al0 + rs0;
            l1[rt] = l1[rt]*al1 + rs1;
        }

        // ---- O += P V : V^T tile, each B load feeds both row-tiles ----
        #pragma unroll
        for (int kc = 0; kc < 4; kc++){
            #pragma unroll
            for (int j = 0; j < 8; j++){
                const unsigned* vr = &Vsb[(8*j + qg)*32];
                int vw = swzA ^ (j & 3);
                unsigned b0 = vr[(8*kc   + rg) ^ vw];
                unsigned b1 = vr[(8*kc+4 + rg) ^ vw];
                mma_f16(o[0][j], pa[0][kc], b0, b1);
                mma_f16(o[1][j], pa[1][kc], b0, b1);
            }
        }
        __syncthreads();   // all warps done with buffer b before it is refilled
    }

    // ---- epilogue: O /= l, write fp32 ----
    float2* Od = (float2*)(Og + base);
    #pragma unroll
    for (int rt = 0; rt < 2; rt++){
        float inv0 = 1.f / l0[rt], inv1 = 1.f / l1[rt];
        const int row0 = qt*128 + w*32 + rt*16 + qg;
        #pragma unroll
        for (int j = 0; j < 8; j++){
            int d = j*8 + 2*rg;
            Od[( row0   *64 + d) >> 1] = make_float2(o[rt][j][0]*inv0, o[rt][j][1]*inv0);
            Od[((row0+8)*64 + d) >> 1] = make_float2(o[rt][j][2]*inv1, o[rt][j][3]*inv1);
        }
    }
}

extern "C" void kernel_launch(void* const* d_in, const int* in_sizes, int n_in,
                              void* d_out, int out_size){
    const float* Q = (const float*)d_in[0];
    const float* K = (const float*)d_in[1];
    const float* V = (const float*)d_in[2];
    float* O = (float*)d_out;

    conv_k<<<(BH_NUM*S_LEN*16)/256, 256>>>(K);
    conv_v<<<(BH_NUM*NT*8)/4, 256>>>(V);
    dim3 grid(S_LEN/128, BH_NUM);   // q-tile fastest -> same-bh CTAs share K/V images in L2
    sdpa_flash_f16_v9<<<grid, 128>>>(Q, O);
}